// round 7
// baseline (speedup 1.0000x reference)
#include <cuda_runtime.h>

#define NN 200000
#define NE 3200000
#define CAP 96
#define NEG_SLOPE 0.02f
#define XT 64            // xgemm tile: nodes per block

// ---- static device scratch (no allocation allowed) ----
__device__ __align__(16) float g_f0[NN * 16];
__device__ __align__(16) float g_f1[NN * 16];
__device__ float g_dinv[NN];
__device__ int   g_cursor[NN];          // after fill: degree (excl. self-loop)
__device__ int   g_csr[(size_t)NN * CAP];

// ---------------- graph build: slot table, no scan ----------------

__global__ void k_zero(int n) {
    int i = blockIdx.x * blockDim.x + threadIdx.x;
    if (i < n) g_cursor[i] = 0;
}

__global__ void k_fill(const int* __restrict__ src, const int* __restrict__ dst, int E) {
    int e = blockIdx.x * blockDim.x + threadIdx.x;
    if (e < E) {
        int d = dst[e];
        int pos = atomicAdd(&g_cursor[d], 1);
        if (pos < CAP) g_csr[(size_t)d * CAP + pos] = src[e];
    }
}

__global__ void k_dinv(int n) {
    int i = blockIdx.x * blockDim.x + threadIdx.x;
    if (i < n) g_dinv[i] = rsqrtf((float)g_cursor[i] + 1.0f);
}

// -------- layer 1 GEMM: f0 = x @ W1, smem-tiled (coalesced, conflict-free) --------
// 64 nodes/block, 4 threads/node, each thread computes 4 outputs.

__global__ void __launch_bounds__(256) k_xgemm(const float* __restrict__ x,
                                               const float* __restrict__ W, int n) {
    __shared__ float Ws[128 * 16];        // 8 KB
    __shared__ float xs[XT * 132];        // 33.8 KB, row stride 132 (528B, 16B-aligned)
    int tid = threadIdx.x;
    for (int i = tid; i < 128 * 16; i += 256) Ws[i] = W[i];

    int base = blockIdx.x * XT;
    int nrows = n - base; if (nrows > XT) nrows = XT;
    const float4* xg = (const float4*)(x + (size_t)base * 128);
    for (int i = tid; i < nrows * 32; i += 256) {
        int r = i >> 5, c = i & 31;
        float4 v = xg[i];                           // flat coalesced stream
        *(float4*)&xs[r * 132 + c * 4] = v;
    }
    __syncthreads();

    int nl = tid >> 2;            // local node 0..63
    int q  = tid & 3;             // output group (4 outputs)
    if (base + nl >= n) return;

    float4 acc = make_float4(0.f, 0.f, 0.f, 0.f);
    const float* xrow = &xs[nl * 132];
#pragma unroll 8
    for (int k4 = 0; k4 < 32; k4++) {
        float4 v  = *(const float4*)&xrow[k4 * 4];
        float4 w0 = *(const float4*)&Ws[(k4 * 4 + 0) * 16 + q * 4];
        float4 w1 = *(const float4*)&Ws[(k4 * 4 + 1) * 16 + q * 4];
        float4 w2 = *(const float4*)&Ws[(k4 * 4 + 2) * 16 + q * 4];
        float4 w3 = *(const float4*)&Ws[(k4 * 4 + 3) * 16 + q * 4];
        acc.x += v.x * w0.x + v.y * w1.x + v.z * w2.x + v.w * w3.x;
        acc.y += v.x * w0.y + v.y * w1.y + v.z * w2.y + v.w * w3.y;
        acc.z += v.x * w0.z + v.y * w1.z + v.z * w2.z + v.w * w3.z;
        acc.w += v.x * w0.w + v.y * w1.w + v.z * w2.w + v.w * w3.w;
    }
    *(float4*)&g_f0[(size_t)(base + nl) * 16 + q * 4] = acc;
}

// -------- fused agg + bias + relu + next GEMM --------
// 16 lanes per node, lane j owns feature j. dir=0: f0->f1, dir=1: f1->f0.

__global__ void __launch_bounds__(256) k_aggf(const float* __restrict__ b,
                                              const float* __restrict__ W,
                                              int n, int dir) {
    __shared__ float Ws[256];
    __shared__ float bs[16];
    Ws[threadIdx.x] = W[threadIdx.x];
    if (threadIdx.x < 16) bs[threadIdx.x] = b[threadIdx.x];
    __syncthreads();

    const float* fsrc = dir ? g_f1 : g_f0;
    float*       fdst = dir ? g_f0 : g_f1;

    int node = blockIdx.x * 16 + (threadIdx.x >> 4);
    int j = threadIdx.x & 15;
    unsigned mask = 0xFFFFu << (threadIdx.x & 16);
    if (node >= n) return;

    float dd = g_dinv[node];
    float acc = dd * dd * fsrc[(size_t)node * 16 + j];   // self loop
    int deg = g_cursor[node];
    if (deg > CAP) deg = CAP;
    const int* row = &g_csr[(size_t)node * CAP];

    int k = 0;
    for (; k + 2 <= deg; k += 2) {
        int sA = row[k];
        int sB = row[k + 1];
        float cA = dd * g_dinv[sA];
        float cB = dd * g_dinv[sB];
        acc += cA * fsrc[(size_t)sA * 16 + j];
        acc += cB * fsrc[(size_t)sB * 16 + j];
    }
    if (k < deg) {
        int sA = row[k];
        acc += dd * g_dinv[sA] * fsrc[(size_t)sA * 16 + j];
    }

    float t = fmaxf(acc + bs[j], 0.0f);   // bias + relu

    float out = 0.0f;
#pragma unroll
    for (int kk = 0; kk < 16; kk++) {
        float tk = __shfl_sync(mask, t, kk, 16);
        out += tk * Ws[kk * 16 + j];
    }
    fdst[(size_t)node * 16 + j] = out;
}

// -------- last aggregation (no relu/gemm): f0 -> f1, pre-bias --------

__global__ void __launch_bounds__(256) k_aggl(int n) {
    int node = blockIdx.x * 16 + (threadIdx.x >> 4);
    int j = threadIdx.x & 15;
    if (node >= n) return;

    float dd = g_dinv[node];
    float acc = dd * dd * g_f0[(size_t)node * 16 + j];
    int deg = g_cursor[node];
    if (deg > CAP) deg = CAP;
    const int* row = &g_csr[(size_t)node * CAP];

    int k = 0;
    for (; k + 2 <= deg; k += 2) {
        int sA = row[k];
        int sB = row[k + 1];
        float cA = dd * g_dinv[sA];
        float cB = dd * g_dinv[sB];
        acc += cA * g_f0[(size_t)sA * 16 + j];
        acc += cB * g_f0[(size_t)sB * 16 + j];
    }
    if (k < deg) {
        int sA = row[k];
        acc += dd * g_dinv[sA] * g_f0[(size_t)sA * 16 + j];
    }
    g_f1[(size_t)node * 16 + j] = acc;
}

// -------- final: h = f1 + b3 ; MLP ; log_softmax -> out --------

__global__ void k_final(const float* __restrict__ b3,
                        const float* __restrict__ M1, const float* __restrict__ mb1,
                        const float* __restrict__ M2, const float* __restrict__ mb2,
                        const float* __restrict__ M3, const float* __restrict__ mb3,
                        float* __restrict__ out, int n) {
    __shared__ float M1s[16 * 64];
    __shared__ float M2s[64 * 16];
    __shared__ float M3s[16 * 2];
    __shared__ float b3s[16], mb1s[64], mb2s[16], mb3s[2];
    for (int i = threadIdx.x; i < 1024; i += blockDim.x) { M1s[i] = M1[i]; M2s[i] = M2[i]; }
    if (threadIdx.x < 32) M3s[threadIdx.x] = M3[threadIdx.x];
    if (threadIdx.x < 16) { b3s[threadIdx.x] = b3[threadIdx.x]; mb2s[threadIdx.x] = mb2[threadIdx.x]; }
    if (threadIdx.x < 64) mb1s[threadIdx.x] = mb1[threadIdx.x];
    if (threadIdx.x < 2) mb3s[threadIdx.x] = mb3[threadIdx.x];
    __syncthreads();

    int node = blockIdx.x * blockDim.x + threadIdx.x;
    if (node >= n) return;

    float t[16];
    const float4* r = (const float4*)&g_f1[(size_t)node * 16];
#pragma unroll
    for (int q = 0; q < 4; q++) {
        float4 v = r[q];
        t[q * 4 + 0] = v.x + b3s[q * 4 + 0];
        t[q * 4 + 1] = v.y + b3s[q * 4 + 1];
        t[q * 4 + 2] = v.z + b3s[q * 4 + 2];
        t[q * 4 + 3] = v.w + b3s[q * 4 + 3];
    }

    float a1[64];
#pragma unroll
    for (int j = 0; j < 64; j++) a1[j] = mb1s[j];
#pragma unroll
    for (int k = 0; k < 16; k++) {
        float tv = t[k];
#pragma unroll
        for (int j = 0; j < 64; j++) a1[j] += tv * M1s[k * 64 + j];
    }
#pragma unroll
    for (int j = 0; j < 64; j++) a1[j] = (a1[j] >= 0.0f) ? a1[j] : a1[j] * NEG_SLOPE;

    float a2[16];
#pragma unroll
    for (int j = 0; j < 16; j++) a2[j] = mb2s[j];
#pragma unroll
    for (int k = 0; k < 64; k++) {
        float av = a1[k];
#pragma unroll
        for (int j = 0; j < 16; j++) a2[j] += av * M2s[k * 16 + j];
    }
#pragma unroll
    for (int j = 0; j < 16; j++) a2[j] = (a2[j] >= 0.0f) ? a2[j] : a2[j] * NEG_SLOPE;

    float l0 = mb3s[0], l1 = mb3s[1];
#pragma unroll
    for (int k = 0; k < 16; k++) {
        l0 += a2[k] * M3s[k * 2 + 0];
        l1 += a2[k] * M3s[k * 2 + 1];
    }
    float m = fmaxf(l0, l1);
    float lse = m + logf(expf(l0 - m) + expf(l1 - m));
    ((float2*)out)[node] = make_float2(l0 - lse, l1 - lse);
}

// ---------------- launch ----------------

extern "C" void kernel_launch(void* const* d_in, const int* in_sizes, int n_in,
                              void* d_out, int out_size) {
    const float* x   = (const float*)d_in[0];
    const int*   dat = (const int*)d_in[1];
    const float* W1  = (const float*)d_in[2];
    const float* b1  = (const float*)d_in[3];
    const float* W2  = (const float*)d_in[4];
    const float* b2  = (const float*)d_in[5];
    const float* W3  = (const float*)d_in[6];
    const float* b3  = (const float*)d_in[7];
    const float* M1  = (const float*)d_in[8];
    const float* mb1 = (const float*)d_in[9];
    const float* M2  = (const float*)d_in[10];
    const float* mb2 = (const float*)d_in[11];
    const float* M3  = (const float*)d_in[12];
    const float* mb3 = (const float*)d_in[13];
    float* out = (float*)d_out;

    int n = in_sizes[0] / 128;
    int E = in_sizes[1] / 2;
    const int* src = dat;
    const int* dst = dat + E;

    int nb = (n + 255) / 256;
    int eb = (E + 255) / 256;
    int xb = (n + XT - 1) / XT;
    int ab = (n + 15) / 16;

    // one-time stream/event setup (host resources only; deterministic work per call)
    static cudaStream_t s_build = nullptr;
    static cudaEvent_t ev_start = nullptr, ev_build = nullptr;
    if (s_build == nullptr) {
        cudaStreamCreateWithFlags(&s_build, cudaStreamNonBlocking);
        cudaEventCreateWithFlags(&ev_start, cudaEventDisableTiming);
        cudaEventCreateWithFlags(&ev_build, cudaEventDisableTiming);
    }

    // fork: graph build on s_build, concurrent with k_xgemm on stream 0
    cudaEventRecord(ev_start, 0);
    cudaStreamWaitEvent(s_build, ev_start, 0);
    k_zero<<<nb, 256, 0, s_build>>>(n);
    k_fill<<<eb, 256, 0, s_build>>>(src, dst, E);
    k_dinv<<<nb, 256, 0, s_build>>>(n);
    cudaEventRecord(ev_build, s_build);

    k_xgemm<<<xb, 256>>>(x, W1, n);

    // join before aggregation needs the graph
    cudaStreamWaitEvent(0, ev_build, 0);

    k_aggf<<<ab, 256>>>(b1, W2, n, 0);   // f0 -> f1
    k_aggf<<<ab, 256>>>(b2, W3, n, 1);   // f1 -> f0
    k_aggl<<<ab, 256>>>(n);              // f0 -> f1 (pre-bias)
    k_final<<<nb, 256>>>(b3, M1, mb1, M2, mb2, M3, mb3, out, n);
}

// round 9
// speedup vs baseline: 1.0801x; 1.0801x over previous
#include <cuda_runtime.h>

#define NN 200000
#define NE 3200000
#define CAP 96
#define NEG_SLOPE 0.02f

// ---- static device scratch (no allocation allowed) ----
__device__ __align__(16) float g_f0[NN * 16];
__device__ __align__(16) float g_f1[NN * 16];
__device__ float g_dinv[NN];
__device__ int   g_cursor[NN];              // after fill: degree (excl. self-loop)
__device__ __align__(16) int g_csr[(size_t)NN * CAP];   // CAP*4=384B rows, 16B aligned

// ---------------- graph build: slot table ----------------

__global__ void k_zero(int n) {
    int i = blockIdx.x * blockDim.x + threadIdx.x;
    if (i < n) g_cursor[i] = 0;
}

__global__ void k_fill(const int* __restrict__ src, const int* __restrict__ dst, int E) {
    int e = blockIdx.x * blockDim.x + threadIdx.x;
    if (e < E) {
        int d = dst[e];
        int pos = atomicAdd(&g_cursor[d], 1);
        if (pos < CAP) g_csr[(size_t)d * CAP + pos] = src[e];
    }
}

__global__ void k_dinv(int n) {
    int i = blockIdx.x * blockDim.x + threadIdx.x;
    if (i < n) g_dinv[i] = rsqrtf((float)g_cursor[i] + 1.0f);
}

// -------- layer 1 GEMM: f0 = x @ W1 (raw). 4 nodes/thread, weights in smem --------

__global__ void __launch_bounds__(256) k_xgemm(const float* __restrict__ x,
                                               const float* __restrict__ W,
                                               int n, int quarter) {
    __shared__ float Ws[128 * 16];
    for (int i = threadIdx.x; i < 128 * 16; i += 256) Ws[i] = W[i];
    __syncthreads();
    int t = blockIdx.x * 256 + threadIdx.x;
    if (t >= quarter) return;

    int nd[4];
    bool ok[4];
#pragma unroll
    for (int p = 0; p < 4; p++) {
        nd[p] = t + p * quarter;
        ok[p] = nd[p] < n;
        if (!ok[p]) nd[p] = t;          // safe fallback address
    }

    float acc[4][16];
#pragma unroll
    for (int p = 0; p < 4; p++)
#pragma unroll
        for (int j = 0; j < 16; j++) acc[p][j] = 0.0f;

    const float4* xr[4];
#pragma unroll
    for (int p = 0; p < 4; p++) xr[p] = (const float4*)(x + (size_t)nd[p] * 128);

#pragma unroll 4
    for (int k4 = 0; k4 < 32; k4++) {
        float4 v[4];
#pragma unroll
        for (int p = 0; p < 4; p++) v[p] = xr[p][k4];
        const float4* wr = (const float4*)&Ws[k4 * 64];
#pragma unroll
        for (int r = 0; r < 4; r++) {
#pragma unroll
            for (int q = 0; q < 4; q++) {
                float4 w = wr[r * 4 + q];
#pragma unroll
                for (int p = 0; p < 4; p++) {
                    float c = (r == 0) ? v[p].x : (r == 1) ? v[p].y : (r == 2) ? v[p].z : v[p].w;
                    acc[p][q * 4 + 0] += c * w.x;
                    acc[p][q * 4 + 1] += c * w.y;
                    acc[p][q * 4 + 2] += c * w.z;
                    acc[p][q * 4 + 3] += c * w.w;
                }
            }
        }
    }

#pragma unroll
    for (int p = 0; p < 4; p++) {
        if (!ok[p]) continue;
        float4* A = (float4*)&g_f0[(size_t)nd[p] * 16];
#pragma unroll
        for (int q = 0; q < 4; q++)
            A[q] = make_float4(acc[p][q * 4], acc[p][q * 4 + 1], acc[p][q * 4 + 2], acc[p][q * 4 + 3]);
    }
}

// -------- establish invariant: f0 *= dinv (f-tilde) --------

__global__ void k_scale(int n) {
    int i = blockIdx.x * blockDim.x + threadIdx.x;   // one float4 per thread
    if (i < n * 4) {
        float d = g_dinv[i >> 2];
        float4 v = ((float4*)g_f0)[i];
        ((float4*)g_f0)[i] = make_float4(v.x * d, v.y * d, v.z * d, v.w * d);
    }
}

// -------- fused agg + bias + relu + GEMM + rescale --------
// Input buffer holds f-tilde = dinv*f. raw = dd*(f~self + sum f~[s]).
// Output written as dinv * (relu(raw+b) @ W)  -> keeps invariant.

__global__ void __launch_bounds__(256) k_aggf(const float* __restrict__ b,
                                              const float* __restrict__ W,
                                              int n, int dir) {
    __shared__ float Ws[256];
    __shared__ float bs[16];
    Ws[threadIdx.x] = W[threadIdx.x];
    if (threadIdx.x < 16) bs[threadIdx.x] = b[threadIdx.x];
    __syncthreads();

    const float* fsrc = dir ? g_f1 : g_f0;
    float*       fdst = dir ? g_f0 : g_f1;

    int node = blockIdx.x * 16 + (threadIdx.x >> 4);
    int j = threadIdx.x & 15;
    unsigned mask = 0xFFFFu << (threadIdx.x & 16);
    if (node >= n) return;

    float sum = fsrc[(size_t)node * 16 + j];    // self (f~)
    int deg = g_cursor[node];
    if (deg > CAP) deg = CAP;
    const int4* rowv = (const int4*)&g_csr[(size_t)node * CAP];
    const int*  row  = (const int*)rowv;

    int k = 0;
    for (; k + 4 <= deg; k += 4) {
        int4 s = rowv[k >> 2];
        sum += fsrc[(size_t)s.x * 16 + j];
        sum += fsrc[(size_t)s.y * 16 + j];
        sum += fsrc[(size_t)s.z * 16 + j];
        sum += fsrc[(size_t)s.w * 16 + j];
    }
    for (; k < deg; k++) sum += fsrc[(size_t)row[k] * 16 + j];

    float dd = g_dinv[node];
    float t = fmaxf(dd * sum + bs[j], 0.0f);    // bias + relu

    float out = 0.0f;
#pragma unroll
    for (int kk = 0; kk < 16; kk++) {
        float tk = __shfl_sync(mask, t, kk, 16);
        out += tk * Ws[kk * 16 + j];
    }
    fdst[(size_t)node * 16 + j] = dd * out;     // rescale -> f~ for next layer
}

// -------- last aggregation: raw output (for MLP), input f~ --------

__global__ void __launch_bounds__(256) k_aggl(int n) {
    int node = blockIdx.x * 16 + (threadIdx.x >> 4);
    int j = threadIdx.x & 15;
    if (node >= n) return;

    float sum = g_f0[(size_t)node * 16 + j];
    int deg = g_cursor[node];
    if (deg > CAP) deg = CAP;
    const int4* rowv = (const int4*)&g_csr[(size_t)node * CAP];
    const int*  row  = (const int*)rowv;

    int k = 0;
    for (; k + 4 <= deg; k += 4) {
        int4 s = rowv[k >> 2];
        sum += g_f0[(size_t)s.x * 16 + j];
        sum += g_f0[(size_t)s.y * 16 + j];
        sum += g_f0[(size_t)s.z * 16 + j];
        sum += g_f0[(size_t)s.w * 16 + j];
    }
    for (; k < deg; k++) sum += g_f0[(size_t)row[k] * 16 + j];

    g_f1[(size_t)node * 16 + j] = g_dinv[node] * sum;   // raw h3
}

// -------- final: h = f1 + b3 ; MLP ; log_softmax -> out --------

__global__ void k_final(const float* __restrict__ b3,
                        const float* __restrict__ M1, const float* __restrict__ mb1,
                        const float* __restrict__ M2, const float* __restrict__ mb2,
                        const float* __restrict__ M3, const float* __restrict__ mb3,
                        float* __restrict__ out, int n) {
    __shared__ float M1s[16 * 64];
    __shared__ float M2s[64 * 16];
    __shared__ float M3s[16 * 2];
    __shared__ float b3s[16], mb1s[64], mb2s[16], mb3s[2];
    for (int i = threadIdx.x; i < 1024; i += blockDim.x) { M1s[i] = M1[i]; M2s[i] = M2[i]; }
    if (threadIdx.x < 32) M3s[threadIdx.x] = M3[threadIdx.x];
    if (threadIdx.x < 16) { b3s[threadIdx.x] = b3[threadIdx.x]; mb2s[threadIdx.x] = mb2[threadIdx.x]; }
    if (threadIdx.x < 64) mb1s[threadIdx.x] = mb1[threadIdx.x];
    if (threadIdx.x < 2) mb3s[threadIdx.x] = mb3[threadIdx.x];
    __syncthreads();

    int node = blockIdx.x * blockDim.x + threadIdx.x;
    if (node >= n) return;

    float t[16];
    const float4* r = (const float4*)&g_f1[(size_t)node * 16];
#pragma unroll
    for (int q = 0; q < 4; q++) {
        float4 v = r[q];
        t[q * 4 + 0] = v.x + b3s[q * 4 + 0];
        t[q * 4 + 1] = v.y + b3s[q * 4 + 1];
        t[q * 4 + 2] = v.z + b3s[q * 4 + 2];
        t[q * 4 + 3] = v.w + b3s[q * 4 + 3];
    }

    float a1[64];
#pragma unroll
    for (int j = 0; j < 64; j++) a1[j] = mb1s[j];
#pragma unroll
    for (int k = 0; k < 16; k++) {
        float tv = t[k];
#pragma unroll
        for (int j = 0; j < 64; j++) a1[j] += tv * M1s[k * 64 + j];
    }
#pragma unroll
    for (int j = 0; j < 64; j++) a1[j] = (a1[j] >= 0.0f) ? a1[j] : a1[j] * NEG_SLOPE;

    float a2[16];
#pragma unroll
    for (int j = 0; j < 16; j++) a2[j] = mb2s[j];
#pragma unroll
    for (int k = 0; k < 64; k++) {
        float av = a1[k];
#pragma unroll
        for (int j = 0; j < 16; j++) a2[j] += av * M2s[k * 16 + j];
    }
#pragma unroll
    for (int j = 0; j < 16; j++) a2[j] = (a2[j] >= 0.0f) ? a2[j] : a2[j] * NEG_SLOPE;

    float l0 = mb3s[0], l1 = mb3s[1];
#pragma unroll
    for (int k = 0; k < 16; k++) {
        l0 += a2[k] * M3s[k * 2 + 0];
        l1 += a2[k] * M3s[k * 2 + 1];
    }
    float m = fmaxf(l0, l1);
    float lse = m + logf(expf(l0 - m) + expf(l1 - m));
    ((float2*)out)[node] = make_float2(l0 - lse, l1 - lse);
}

// ---------------- launch ----------------

extern "C" void kernel_launch(void* const* d_in, const int* in_sizes, int n_in,
                              void* d_out, int out_size) {
    const float* x   = (const float*)d_in[0];
    const int*   dat = (const int*)d_in[1];
    const float* W1  = (const float*)d_in[2];
    const float* b1  = (const float*)d_in[3];
    const float* W2  = (const float*)d_in[4];
    const float* b2  = (const float*)d_in[5];
    const float* W3  = (const float*)d_in[6];
    const float* b3  = (const float*)d_in[7];
    const float* M1  = (const float*)d_in[8];
    const float* mb1 = (const float*)d_in[9];
    const float* M2  = (const float*)d_in[10];
    const float* mb2 = (const float*)d_in[11];
    const float* M3  = (const float*)d_in[12];
    const float* mb3 = (const float*)d_in[13];
    float* out = (float*)d_out;

    int n = in_sizes[0] / 128;
    int E = in_sizes[1] / 2;
    const int* src = dat;
    const int* dst = dat + E;

    int nb = (n + 255) / 256;
    int eb = (E + 255) / 256;
    int quarter = (n + 3) / 4;
    int xb = (quarter + 255) / 256;
    int ab = (n + 15) / 16;
    int scb = (n * 4 + 255) / 256;

    static cudaStream_t s_build = nullptr;
    static cudaEvent_t ev_start = nullptr, ev_build = nullptr;
    if (s_build == nullptr) {
        cudaStreamCreateWithFlags(&s_build, cudaStreamNonBlocking);
        cudaEventCreateWithFlags(&ev_start, cudaEventDisableTiming);
        cudaEventCreateWithFlags(&ev_build, cudaEventDisableTiming);
    }

    // fork: graph build concurrent with xgemm
    cudaEventRecord(ev_start, 0);
    cudaStreamWaitEvent(s_build, ev_start, 0);
    k_zero<<<nb, 256, 0, s_build>>>(n);
    k_fill<<<eb, 256, 0, s_build>>>(src, dst, E);
    k_dinv<<<nb, 256, 0, s_build>>>(n);
    cudaEventRecord(ev_build, s_build);

    k_xgemm<<<xb, 256>>>(x, W1, n, quarter);

    cudaStreamWaitEvent(0, ev_build, 0);

    k_scale<<<scb, 256>>>(n);            // f0 -> f~
    k_aggf<<<ab, 256>>>(b1, W2, n, 0);   // f0 -> f1 (f~)
    k_aggf<<<ab, 256>>>(b2, W3, n, 1);   // f1 -> f0 (f~)
    k_aggl<<<ab, 256>>>(n);              // f0 -> f1 (raw)
    k_final<<<nb, 256>>>(b3, M1, mb1, M2, mb2, M3, mb3, out, n);
}

// round 10
// speedup vs baseline: 1.1993x; 1.1103x over previous
#include <cuda_runtime.h>

#define NN 200000
#define NE 3200000
#define CAP 96
#define NEG_SLOPE 0.02f

// ---- static device scratch (no allocation allowed) ----
__device__ __align__(16) float g_f0[NN * 16];
__device__ __align__(16) float g_f1[NN * 16];
__device__ float g_dinv[NN];
__device__ int   g_cursor[NN];              // after fill: degree (excl. self-loop)
__device__ __align__(16) int g_csr[(size_t)NN * CAP];

// ---------------- graph build: slot table ----------------

__global__ void k_zero(int n) {
    int i = blockIdx.x * blockDim.x + threadIdx.x;
    if (i < n) g_cursor[i] = 0;
}

__global__ void k_fill(const int* __restrict__ src, const int* __restrict__ dst, int E) {
    int e = blockIdx.x * blockDim.x + threadIdx.x;
    if (e < E) {
        int d = dst[e];
        int pos = atomicAdd(&g_cursor[d], 1);
        if (pos < CAP) g_csr[(size_t)d * CAP + pos] = src[e];
    }
}

__global__ void k_dinv(int n) {
    int i = blockIdx.x * blockDim.x + threadIdx.x;
    if (i < n) g_dinv[i] = rsqrtf((float)g_cursor[i] + 1.0f);
}

// -------- layer 1 GEMM: f0 = x @ W1 (raw). 2 nodes/thread, 50% occ cap --------

__global__ void __launch_bounds__(256, 4) k_xgemm(const float* __restrict__ x,
                                                  const float* __restrict__ W,
                                                  int n, int half) {
    __shared__ float Ws[128 * 16];
    for (int i = threadIdx.x; i < 128 * 16; i += 256) Ws[i] = W[i];
    __syncthreads();
    int t = blockIdx.x * 256 + threadIdx.x;
    if (t >= half) return;
    int n0 = t;
    int n1 = t + half;
    bool has1 = (n1 < n);
    int n1c = has1 ? n1 : n0;

    float acc0[16], acc1[16];
#pragma unroll
    for (int j = 0; j < 16; j++) { acc0[j] = 0.0f; acc1[j] = 0.0f; }

    const float4* xr0 = (const float4*)(x + (size_t)n0 * 128);
    const float4* xr1 = (const float4*)(x + (size_t)n1c * 128);
#pragma unroll 4
    for (int k4 = 0; k4 < 32; k4++) {
        float4 a = xr0[k4];
        float4 b = xr1[k4];
        const float4* wr = (const float4*)&Ws[k4 * 64];
#pragma unroll
        for (int r = 0; r < 4; r++) {
            float ca = (r == 0) ? a.x : (r == 1) ? a.y : (r == 2) ? a.z : a.w;
            float cb = (r == 0) ? b.x : (r == 1) ? b.y : (r == 2) ? b.z : b.w;
#pragma unroll
            for (int q = 0; q < 4; q++) {
                float4 w = wr[r * 4 + q];
                acc0[q * 4 + 0] += ca * w.x; acc0[q * 4 + 1] += ca * w.y;
                acc0[q * 4 + 2] += ca * w.z; acc0[q * 4 + 3] += ca * w.w;
                acc1[q * 4 + 0] += cb * w.x; acc1[q * 4 + 1] += cb * w.y;
                acc1[q * 4 + 2] += cb * w.z; acc1[q * 4 + 3] += cb * w.w;
            }
        }
    }

    float4* A = (float4*)&g_f0[(size_t)n0 * 16];
#pragma unroll
    for (int q = 0; q < 4; q++)
        A[q] = make_float4(acc0[q * 4], acc0[q * 4 + 1], acc0[q * 4 + 2], acc0[q * 4 + 3]);
    if (has1) {
        float4* B = (float4*)&g_f0[(size_t)n1 * 16];
#pragma unroll
        for (int q = 0; q < 4; q++)
            B[q] = make_float4(acc1[q * 4], acc1[q * 4 + 1], acc1[q * 4 + 2], acc1[q * 4 + 3]);
    }
}

// -------- establish invariant: f0 *= dinv (f-tilde) --------

__global__ void k_scale(int n) {
    int i = blockIdx.x * blockDim.x + threadIdx.x;   // one float4 per thread
    if (i < n * 4) {
        float d = g_dinv[i >> 2];
        float4 v = ((float4*)g_f0)[i];
        ((float4*)g_f0)[i] = make_float4(v.x * d, v.y * d, v.z * d, v.w * d);
    }
}

// -------- fused agg + bias + relu + GEMM + rescale --------
// 8 lanes per node; lane owns features {2j, 2j+1} (float2).
// Input holds f~ = dinv*f. raw = dd*(f~self + sum f~[s]).
// Output = dinv * (relu(raw+b) @ W).

__global__ void __launch_bounds__(256) k_aggf(const float* __restrict__ b,
                                              const float* __restrict__ W,
                                              int n, int dir) {
    __shared__ float Ws[256];
    __shared__ float bs[16];
    Ws[threadIdx.x] = W[threadIdx.x];
    if (threadIdx.x < 16) bs[threadIdx.x] = b[threadIdx.x];
    __syncthreads();

    const float* fsrc = dir ? g_f1 : g_f0;
    float*       fdst = dir ? g_f0 : g_f1;

    int node = blockIdx.x * 32 + (threadIdx.x >> 3);
    int j2 = threadIdx.x & 7;                     // float2 slot: features 2*j2, 2*j2+1
    unsigned mask = 0xFFu << (threadIdx.x & 24);  // width-8 group mask
    if (node >= n) return;

    const float2* fs2 = (const float2*)fsrc;
    float2 sum = fs2[(size_t)node * 8 + j2];      // self (f~)
    int deg = g_cursor[node];
    if (deg > CAP) deg = CAP;
    const int4* rowv = (const int4*)&g_csr[(size_t)node * CAP];
    const int*  row  = (const int*)rowv;

    int k = 0;
    for (; k + 4 <= deg; k += 4) {
        int4 s = rowv[k >> 2];
        float2 vA = fs2[(size_t)s.x * 8 + j2];
        float2 vB = fs2[(size_t)s.y * 8 + j2];
        float2 vC = fs2[(size_t)s.z * 8 + j2];
        float2 vD = fs2[(size_t)s.w * 8 + j2];
        sum.x += vA.x + vB.x + vC.x + vD.x;
        sum.y += vA.y + vB.y + vC.y + vD.y;
    }
    for (; k < deg; k++) {
        float2 v = fs2[(size_t)row[k] * 8 + j2];
        sum.x += v.x; sum.y += v.y;
    }

    float dd = g_dinv[node];
    int j0 = j2 * 2;
    float t0 = fmaxf(dd * sum.x + bs[j0], 0.0f);
    float t1 = fmaxf(dd * sum.y + bs[j0 + 1], 0.0f);

    // 16x16 GEMM across 8-lane group: out_j = sum_k t_k * W[k][j]
    float o0 = 0.0f, o1 = 0.0f;
#pragma unroll
    for (int kk = 0; kk < 8; kk++) {
        float ta = __shfl_sync(mask, t0, kk, 8);   // t[2kk]
        float tb = __shfl_sync(mask, t1, kk, 8);   // t[2kk+1]
        o0 += ta * Ws[(2 * kk) * 16 + j0]     + tb * Ws[(2 * kk + 1) * 16 + j0];
        o1 += ta * Ws[(2 * kk) * 16 + j0 + 1] + tb * Ws[(2 * kk + 1) * 16 + j0 + 1];
    }
    ((float2*)fdst)[(size_t)node * 8 + j2] = make_float2(dd * o0, dd * o1);
}

// -------- last aggregation: raw output (for MLP), input f~ --------

__global__ void __launch_bounds__(256) k_aggl(int n) {
    int node = blockIdx.x * 32 + (threadIdx.x >> 3);
    int j2 = threadIdx.x & 7;
    if (node >= n) return;

    const float2* fs2 = (const float2*)g_f0;
    float2 sum = fs2[(size_t)node * 8 + j2];
    int deg = g_cursor[node];
    if (deg > CAP) deg = CAP;
    const int4* rowv = (const int4*)&g_csr[(size_t)node * CAP];
    const int*  row  = (const int*)rowv;

    int k = 0;
    for (; k + 4 <= deg; k += 4) {
        int4 s = rowv[k >> 2];
        float2 vA = fs2[(size_t)s.x * 8 + j2];
        float2 vB = fs2[(size_t)s.y * 8 + j2];
        float2 vC = fs2[(size_t)s.z * 8 + j2];
        float2 vD = fs2[(size_t)s.w * 8 + j2];
        sum.x += vA.x + vB.x + vC.x + vD.x;
        sum.y += vA.y + vB.y + vC.y + vD.y;
    }
    for (; k < deg; k++) {
        float2 v = fs2[(size_t)row[k] * 8 + j2];
        sum.x += v.x; sum.y += v.y;
    }

    float dd = g_dinv[node];
    ((float2*)g_f1)[(size_t)node * 8 + j2] = make_float2(dd * sum.x, dd * sum.y);
}

// -------- final: h = f1 + b3 ; MLP ; log_softmax -> out --------

__global__ void k_final(const float* __restrict__ b3,
                        const float* __restrict__ M1, const float* __restrict__ mb1,
                        const float* __restrict__ M2, const float* __restrict__ mb2,
                        const float* __restrict__ M3, const float* __restrict__ mb3,
                        float* __restrict__ out, int n) {
    __shared__ float M1s[16 * 64];
    __shared__ float M2s[64 * 16];
    __shared__ float M3s[16 * 2];
    __shared__ float b3s[16], mb1s[64], mb2s[16], mb3s[2];
    for (int i = threadIdx.x; i < 1024; i += blockDim.x) { M1s[i] = M1[i]; M2s[i] = M2[i]; }
    if (threadIdx.x < 32) M3s[threadIdx.x] = M3[threadIdx.x];
    if (threadIdx.x < 16) { b3s[threadIdx.x] = b3[threadIdx.x]; mb2s[threadIdx.x] = mb2[threadIdx.x]; }
    if (threadIdx.x < 64) mb1s[threadIdx.x] = mb1[threadIdx.x];
    if (threadIdx.x < 2) mb3s[threadIdx.x] = mb3[threadIdx.x];
    __syncthreads();

    int node = blockIdx.x * blockDim.x + threadIdx.x;
    if (node >= n) return;

    float t[16];
    const float4* r = (const float4*)&g_f1[(size_t)node * 16];
#pragma unroll
    for (int q = 0; q < 4; q++) {
        float4 v = r[q];
        t[q * 4 + 0] = v.x + b3s[q * 4 + 0];
        t[q * 4 + 1] = v.y + b3s[q * 4 + 1];
        t[q * 4 + 2] = v.z + b3s[q * 4 + 2];
        t[q * 4 + 3] = v.w + b3s[q * 4 + 3];
    }

    float a1[64];
#pragma unroll
    for (int j = 0; j < 64; j++) a1[j] = mb1s[j];
#pragma unroll
    for (int k = 0; k < 16; k++) {
        float tv = t[k];
#pragma unroll
        for (int j = 0; j < 64; j++) a1[j] += tv * M1s[k * 64 + j];
    }
#pragma unroll
    for (int j = 0; j < 64; j++) a1[j] = (a1[j] >= 0.0f) ? a1[j] : a1[j] * NEG_SLOPE;

    float a2[16];
#pragma unroll
    for (int j = 0; j < 16; j++) a2[j] = mb2s[j];
#pragma unroll
    for (int k = 0; k < 64; k++) {
        float av = a1[k];
#pragma unroll
        for (int j = 0; j < 16; j++) a2[j] += av * M2s[k * 16 + j];
    }
#pragma unroll
    for (int j = 0; j < 16; j++) a2[j] = (a2[j] >= 0.0f) ? a2[j] : a2[j] * NEG_SLOPE;

    float l0 = mb3s[0], l1 = mb3s[1];
#pragma unroll
    for (int k = 0; k < 16; k++) {
        l0 += a2[k] * M3s[k * 2 + 0];
        l1 += a2[k] * M3s[k * 2 + 1];
    }
    float m = fmaxf(l0, l1);
    float lse = m + logf(expf(l0 - m) + expf(l1 - m));
    ((float2*)out)[node] = make_float2(l0 - lse, l1 - lse);
}

// ---------------- launch ----------------

extern "C" void kernel_launch(void* const* d_in, const int* in_sizes, int n_in,
                              void* d_out, int out_size) {
    const float* x   = (const float*)d_in[0];
    const int*   dat = (const int*)d_in[1];
    const float* W1  = (const float*)d_in[2];
    const float* b1  = (const float*)d_in[3];
    const float* W2  = (const float*)d_in[4];
    const float* b2  = (const float*)d_in[5];
    const float* W3  = (const float*)d_in[6];
    const float* b3  = (const float*)d_in[7];
    const float* M1  = (const float*)d_in[8];
    const float* mb1 = (const float*)d_in[9];
    const float* M2  = (const float*)d_in[10];
    const float* mb2 = (const float*)d_in[11];
    const float* M3  = (const float*)d_in[12];
    const float* mb3 = (const float*)d_in[13];
    float* out = (float*)d_out;

    int n = in_sizes[0] / 128;
    int E = in_sizes[1] / 2;
    const int* src = dat;
    const int* dst = dat + E;

    int nb = (n + 255) / 256;
    int eb = (E + 255) / 256;
    int half = (n + 1) / 2;
    int xb = (half + 255) / 256;
    int ab = (n + 31) / 32;
    int scb = (n * 4 + 255) / 256;

    static cudaStream_t s_build = nullptr;
    static cudaEvent_t ev_start = nullptr, ev_build = nullptr;
    if (s_build == nullptr) {
        cudaStreamCreateWithFlags(&s_build, cudaStreamNonBlocking);
        cudaEventCreateWithFlags(&ev_start, cudaEventDisableTiming);
        cudaEventCreateWithFlags(&ev_build, cudaEventDisableTiming);
    }

    // fork: graph build concurrent with xgemm
    cudaEventRecord(ev_start, 0);
    cudaStreamWaitEvent(s_build, ev_start, 0);
    k_zero<<<nb, 256, 0, s_build>>>(n);
    k_fill<<<eb, 256, 0, s_build>>>(src, dst, E);
    k_dinv<<<nb, 256, 0, s_build>>>(n);
    cudaEventRecord(ev_build, s_build);

    k_xgemm<<<xb, 256>>>(x, W1, n, half);

    cudaStreamWaitEvent(0, ev_build, 0);

    k_scale<<<scb, 256>>>(n);            // f0 -> f~
    k_aggf<<<ab, 256>>>(b1, W2, n, 0);   // f0 -> f1 (f~)
    k_aggf<<<ab, 256>>>(b2, W3, n, 1);   // f1 -> f0 (f~)
    k_aggl<<<ab, 256>>>(n);              // f0 -> f1 (raw)
    k_final<<<nb, 256>>>(b3, M1, mb1, M2, mb2, M3, mb3, out, n);
}